// round 5
// baseline (speedup 1.0000x reference)
#include <cuda_runtime.h>
#include <cstdint>

#define NMAX   100000
#define EMAX   1600000
#define DIN    128
#define DH     128
#define DOUT   16

// 16B-aligned scratch (float4 stores + red.global.add.v4.f32 require it)
__device__ __align__(16) float g_deg[NMAX];              // degree, then dinv in place
__device__ __align__(16) float g_h1[(size_t)NMAX * DH];  // x @ W1
__device__ __align__(16) float g_agg1[(size_t)NMAX * DH];// edge-aggregated layer-1
__device__ __align__(16) float g_h2[(size_t)NMAX * DOUT];// relu(...) @ W2
__device__ int g_is64;                                   // edge_index dtype flag

// ---------------- helpers ---------------------------------------------------
__device__ __forceinline__ void red_add_v4(float* p, float4 v) {
#if __CUDA_ARCH__ >= 900
    asm volatile("red.global.add.v4.f32 [%0], {%1,%2,%3,%4};"
                 :: "l"(p), "f"(v.x), "f"(v.y), "f"(v.z), "f"(v.w) : "memory");
#else
    atomicAdd(p + 0, v.x); atomicAdd(p + 1, v.y);
    atomicAdd(p + 2, v.z); atomicAdd(p + 3, v.w);
#endif
}

// dtype-agnostic edge-index load: ei holds 2*e indices (src row then dst row)
__device__ __forceinline__ int load_idx(const void* __restrict__ ei, long long i) {
    if (g_is64) return (int)__ldg(((const long long*)ei) + i);
    return __ldg(((const int*)ei) + i);
}

// ---------------- kernels ---------------------------------------------------

// Detect int64 vs int32 edge_index. Indices < 100000 < 2^32, so genuine int64
// data has zero high words; packed int32 data puts a random index in the high
// word (nonzero w.p. ~1-1e-5 per element; 64 checks -> certain).
__global__ void k_detect(const void* __restrict__ ei) {
    const unsigned long long* p = (const unsigned long long*)ei;
    int is64 = 1;
    for (int i = 0; i < 64; i++)
        if ((p[i] >> 32) != 0ull) { is64 = 0; break; }
    g_is64 = is64;
}

__global__ void k_set_deg_one(int n) {
    int i = blockIdx.x * blockDim.x + threadIdx.x;
    if (i < n) g_deg[i] = 1.0f;
}

__global__ void k_zero_agg1(int n4) {
    int i = blockIdx.x * blockDim.x + threadIdx.x;
    if (i < n4) reinterpret_cast<float4*>(g_agg1)[i] = make_float4(0.f, 0.f, 0.f, 0.f);
}

__global__ void k_deg_count(const void* __restrict__ ei, int e) {
    int i = blockIdx.x * blockDim.x + threadIdx.x;
    if (i < e) atomicAdd(&g_deg[load_idx(ei, (long long)e + i)], 1.0f);
}

__global__ void k_rsqrt(int n) {
    int i = blockIdx.x * blockDim.x + threadIdx.x;
    if (i < n) g_deg[i] = rsqrtf(g_deg[i]);
}

// h1 = x @ W1 : 64x128 tile per block, 256 threads, each thread 8 rows x 4 cols
#define GTM 64
__global__ void k_gemm1(const float* __restrict__ x,
                        const float* __restrict__ W1, int n) {
    extern __shared__ float sm[];
    float* Ws = sm;                 // 128*128
    float* Xs = sm + DIN * DH;      // GTM*128
    int t = threadIdx.x;

    for (int i = t; i < DIN * DH / 4; i += 256)
        reinterpret_cast<float4*>(Ws)[i] = reinterpret_cast<const float4*>(W1)[i];

    int row0 = blockIdx.x * GTM;
    for (int i = t; i < GTM * DIN / 4; i += 256) {
        int r = i >> 5, c4 = i & 31;
        int gr = row0 + r;
        float4 v = make_float4(0.f, 0.f, 0.f, 0.f);
        if (gr < n) v = reinterpret_cast<const float4*>(x)[(size_t)gr * 32 + c4];
        reinterpret_cast<float4*>(Xs)[i] = v;
    }
    __syncthreads();

    int cx = t & 31;
    int ry = t >> 5;
    float acc[8][4];
#pragma unroll
    for (int r = 0; r < 8; r++)
#pragma unroll
        for (int c = 0; c < 4; c++) acc[r][c] = 0.f;

#pragma unroll 4
    for (int k = 0; k < DIN; k++) {
        float4 w = reinterpret_cast<const float4*>(Ws)[k * 32 + cx];
#pragma unroll
        for (int r = 0; r < 8; r++) {
            float a = Xs[(ry * 8 + r) * DIN + k];   // warp-uniform broadcast
            acc[r][0] = fmaf(a, w.x, acc[r][0]);
            acc[r][1] = fmaf(a, w.y, acc[r][1]);
            acc[r][2] = fmaf(a, w.z, acc[r][2]);
            acc[r][3] = fmaf(a, w.w, acc[r][3]);
        }
    }
#pragma unroll
    for (int r = 0; r < 8; r++) {
        int gr = row0 + ry * 8 + r;
        if (gr < n)
            reinterpret_cast<float4*>(g_h1)[(size_t)gr * 32 + cx] =
                make_float4(acc[r][0], acc[r][1], acc[r][2], acc[r][3]);
    }
}

// one warp per edge; lane handles one float4 of the 128-dim message
__global__ void k_scatter1(const void* __restrict__ ei, int e) {
    long long tid = (long long)blockIdx.x * blockDim.x + threadIdx.x;
    long long eid = tid >> 5;
    int lane = threadIdx.x & 31;
    if (eid >= e) return;
    int s = load_idx(ei, eid);
    int d = load_idx(ei, (long long)e + eid);
    float w = g_deg[s] * g_deg[d];
    float4 v = reinterpret_cast<const float4*>(g_h1)[(size_t)s * 32 + lane];
    v.x *= w; v.y *= w; v.z *= w; v.w *= w;
    red_add_v4(&g_agg1[(size_t)d * DH + lane * 4], v);
}

// fused: v = relu(agg1 + h1*dinv^2 + b1); h2 = v @ W2
__global__ void k_relu_gemm2(const float* __restrict__ b1,
                             const float* __restrict__ W2, int n) {
    __shared__ float W2s[DH * DOUT];
    __shared__ float b1s[DH];
    int t = threadIdx.x;
    for (int i = t; i < DH * DOUT; i += 256) W2s[i] = W2[i];
    if (t < DH) b1s[t] = b1[t];
    __syncthreads();

    int node = blockIdx.x * 16 + (t >> 4);
    int j = t & 15;
    if (node >= n) return;
    float di = g_deg[node];
    float dd = di * di;
    const float4* ag = reinterpret_cast<const float4*>(g_agg1 + (size_t)node * DH);
    const float4* hh = reinterpret_cast<const float4*>(g_h1 + (size_t)node * DH);
    float acc = 0.f;
#pragma unroll 8
    for (int k4 = 0; k4 < DH / 4; k4++) {
        float4 a = ag[k4];
        float4 h = hh[k4];
        float v0 = fmaxf(fmaf(h.x, dd, a.x) + b1s[k4 * 4 + 0], 0.f);
        float v1 = fmaxf(fmaf(h.y, dd, a.y) + b1s[k4 * 4 + 1], 0.f);
        float v2 = fmaxf(fmaf(h.z, dd, a.z) + b1s[k4 * 4 + 2], 0.f);
        float v3 = fmaxf(fmaf(h.w, dd, a.w) + b1s[k4 * 4 + 3], 0.f);
        acc = fmaf(v0, W2s[(k4 * 4 + 0) * DOUT + j], acc);
        acc = fmaf(v1, W2s[(k4 * 4 + 1) * DOUT + j], acc);
        acc = fmaf(v2, W2s[(k4 * 4 + 2) * DOUT + j], acc);
        acc = fmaf(v3, W2s[(k4 * 4 + 3) * DOUT + j], acc);
    }
    g_h2[(size_t)node * DOUT + j] = acc;
}

// out[i,j] = b2[j] + h2[i,j] * dinv[i]^2  (layer-2 self-loop folded in)
__global__ void k_out_init(float* __restrict__ out, const float* __restrict__ b2, int n) {
    int i = blockIdx.x * blockDim.x + threadIdx.x;
    if (i < n * DOUT) {
        int node = i >> 4, j = i & 15;
        float di = g_deg[node];
        out[i] = fmaf(g_h2[i], di * di, b2[j]);
    }
}

// 4 threads per edge, one float4 each of the 16-dim message
__global__ void k_scatter2(const void* __restrict__ ei,
                           float* __restrict__ out, int e) {
    long long tid = (long long)blockIdx.x * blockDim.x + threadIdx.x;
    long long eid = tid >> 2;
    int chunk = (int)(tid & 3);
    if (eid >= e) return;
    int s = load_idx(ei, eid);
    int d = load_idx(ei, (long long)e + eid);
    float w = g_deg[s] * g_deg[d];
    float4 v = reinterpret_cast<const float4*>(g_h2)[(size_t)s * 4 + chunk];
    v.x *= w; v.y *= w; v.z *= w; v.w *= w;
    red_add_v4(&out[(size_t)d * DOUT + chunk * 4], v);
}

// ---------------- launch -----------------------------------------------------
extern "C" void kernel_launch(void* const* d_in, const int* in_sizes, int n_in,
                              void* d_out, int out_size) {
    const float* x  = (const float*)d_in[0];
    const void*  ei = d_in[1];                  // [2,E], int64 OR int32 (detected)
    const float* W1 = (const float*)d_in[2];
    const float* b1 = (const float*)d_in[3];
    const float* W2 = (const float*)d_in[4];
    const float* b2 = (const float*)d_in[5];
    float* out = (float*)d_out;

    int n = in_sizes[0] / DIN;
    int e = in_sizes[1] / 2;

    k_detect<<<1, 1>>>(ei);

    k_set_deg_one<<<(n + 255) / 256, 256>>>(n);
    k_deg_count<<<(e + 255) / 256, 256>>>(ei, e);
    k_rsqrt<<<(n + 255) / 256, 256>>>(n);

    int n4 = n * (DH / 4);
    k_zero_agg1<<<(n4 + 255) / 256, 256>>>(n4);

    int smem = (DIN * DH + GTM * DIN) * (int)sizeof(float);   // 96 KB
    cudaFuncSetAttribute(k_gemm1, cudaFuncAttributeMaxDynamicSharedMemorySize, smem);
    k_gemm1<<<(n + GTM - 1) / GTM, 256, smem>>>(x, W1, n);

    long long thr1 = (long long)e * 32;
    k_scatter1<<<(unsigned)((thr1 + 255) / 256), 256>>>(ei, e);

    k_relu_gemm2<<<(n + 15) / 16, 256>>>(b1, W2, n);

    k_out_init<<<(n * DOUT + 255) / 256, 256>>>(out, b2, n);
    long long thr2 = (long long)e * 4;
    k_scatter2<<<(unsigned)((thr2 + 255) / 256), 256>>>(ei, out, e);
}

// round 6
// speedup vs baseline: 1.9222x; 1.9222x over previous
#include <cuda_runtime.h>
#include <cstdint>

#define NMAX   100000
#define EMAX   1600000
#define DIN    128
#define DH     128
#define DOUT   16

// ---------------- device scratch (16B-aligned where vector-accessed) --------
__device__ __align__(16) float g_deg[NMAX];               // dinv = rsqrt(deg)
__device__ __align__(16) float g_h1[(size_t)NMAX * DH];   // x @ W1
__device__ __align__(16) float g_agg1[(size_t)NMAX * DH]; // normalized edge agg, layer 1
__device__ __align__(16) float g_h2[(size_t)NMAX * DOUT]; // relu(...) @ W2
__device__ int g_src[EMAX];
__device__ int g_dst[EMAX];
__device__ int g_csr[EMAX];      // src indices grouped by dst
__device__ int g_cnt[NMAX];      // in-degree (real edges only)
__device__ int g_row[NMAX];      // CSR row starts (exclusive scan of cnt)
__device__ int g_cur[NMAX];      // fill cursors
__device__ int g_excl[NMAX];     // per-block exclusive scan
__device__ int g_bsum[128];      // block sums (<= 98 blocks of 1024)
__device__ int g_is64;

// ---------------- helpers ---------------------------------------------------
__device__ __forceinline__ int load_idx(const void* __restrict__ ei, long long i) {
    if (g_is64) return (int)__ldg(((const long long*)ei) + i);
    return __ldg(((const int*)ei) + i);
}

// ---------------- CSR construction ------------------------------------------
__global__ void k_detect(const void* __restrict__ ei) {
    const unsigned long long* p = (const unsigned long long*)ei;
    int is64 = 1;
    for (int i = 0; i < 64; i++)
        if ((p[i] >> 32) != 0ull) { is64 = 0; break; }
    g_is64 = is64;
}

// int64/int32 -> int32 src/dst; also zero the histogram
__global__ void k_convert(const void* __restrict__ ei, int e, int n) {
    int i = blockIdx.x * blockDim.x + threadIdx.x;
    if (i < e) {
        g_src[i] = load_idx(ei, i);
        g_dst[i] = load_idx(ei, (long long)e + i);
    }
    if (i < n) g_cnt[i] = 0;
}

__global__ void k_count(int e) {
    int i = blockIdx.x * blockDim.x + threadIdx.x;
    if (i < e) atomicAdd(&g_cnt[g_dst[i]], 1);
}

// block-level exclusive scan: 1024 elements per block (256 thr x 4)
__global__ void k_scan1(int n) {
    __shared__ int sh[256];
    int t = threadIdx.x;
    int base = blockIdx.x * 1024;
    int v[4], s = 0;
#pragma unroll
    for (int i = 0; i < 4; i++) {
        int idx = base + t * 4 + i;
        v[i] = (idx < n) ? g_cnt[idx] : 0;
        s += v[i];
    }
    sh[t] = s;
    __syncthreads();
    int own = s;
    for (int off = 1; off < 256; off <<= 1) {
        int o = (t >= off) ? sh[t - off] : 0;
        __syncthreads();
        sh[t] += o;
        __syncthreads();
    }
    if (t == 255) g_bsum[blockIdx.x] = sh[255];
    int run = sh[t] - own;   // exclusive prefix of this thread's 4 elems
#pragma unroll
    for (int i = 0; i < 4; i++) {
        int idx = base + t * 4 + i;
        if (idx < n) g_excl[idx] = run;
        run += v[i];
    }
}

// scan the (<=128) block sums in place -> exclusive
__global__ void k_scan2(int nb) {
    __shared__ int sh[128];
    int t = threadIdx.x;
    int v = (t < nb) ? g_bsum[t] : 0;
    sh[t] = v;
    __syncthreads();
    for (int off = 1; off < 128; off <<= 1) {
        int o = (t >= off) ? sh[t - off] : 0;
        __syncthreads();
        sh[t] += o;
        __syncthreads();
    }
    if (t < nb) g_bsum[t] = sh[t] - v;
}

// finalize row starts + cursors, and compute dinv = rsqrt(deg+1) (self-loop)
__global__ void k_scan3(int n) {
    int i = blockIdx.x * blockDim.x + threadIdx.x;
    if (i < n) {
        int r = g_excl[i] + g_bsum[i >> 10];
        g_row[i] = r;
        g_cur[i] = r;
        g_deg[i] = rsqrtf((float)g_cnt[i] + 1.0f);
    }
}

__global__ void k_fill(int e) {
    int i = blockIdx.x * blockDim.x + threadIdx.x;
    if (i < e) {
        int d = g_dst[i];
        int pos = atomicAdd(&g_cur[d], 1);
        g_csr[pos] = g_src[i];
    }
}

// ---------------- GEMM1: h1 = x @ W1 ----------------------------------------
#define GTM 64
__global__ void k_gemm1(const float* __restrict__ x,
                        const float* __restrict__ W1, int n) {
    extern __shared__ float sm[];
    float* Ws = sm;                 // 128*128
    float* Xs = sm + DIN * DH;      // GTM*128
    int t = threadIdx.x;

    for (int i = t; i < DIN * DH / 4; i += 256)
        reinterpret_cast<float4*>(Ws)[i] = reinterpret_cast<const float4*>(W1)[i];

    int row0 = blockIdx.x * GTM;
    for (int i = t; i < GTM * DIN / 4; i += 256) {
        int r = i >> 5, c4 = i & 31;
        int gr = row0 + r;
        float4 v = make_float4(0.f, 0.f, 0.f, 0.f);
        if (gr < n) v = reinterpret_cast<const float4*>(x)[(size_t)gr * 32 + c4];
        reinterpret_cast<float4*>(Xs)[i] = v;
    }
    __syncthreads();

    int cx = t & 31;
    int ry = t >> 5;
    float acc[8][4];
#pragma unroll
    for (int r = 0; r < 8; r++)
#pragma unroll
        for (int c = 0; c < 4; c++) acc[r][c] = 0.f;

#pragma unroll 4
    for (int k = 0; k < DIN; k++) {
        float4 w = reinterpret_cast<const float4*>(Ws)[k * 32 + cx];
#pragma unroll
        for (int r = 0; r < 8; r++) {
            float a = Xs[(ry * 8 + r) * DIN + k];   // warp-uniform broadcast
            acc[r][0] = fmaf(a, w.x, acc[r][0]);
            acc[r][1] = fmaf(a, w.y, acc[r][1]);
            acc[r][2] = fmaf(a, w.z, acc[r][2]);
            acc[r][3] = fmaf(a, w.w, acc[r][3]);
        }
    }
#pragma unroll
    for (int r = 0; r < 8; r++) {
        int gr = row0 + ry * 8 + r;
        if (gr < n)
            reinterpret_cast<float4*>(g_h1)[(size_t)gr * 32 + cx] =
                make_float4(acc[r][0], acc[r][1], acc[r][2], acc[r][3]);
    }
}

// ---------------- layer-1 aggregation: one warp per node, no atomics --------
__global__ void k_agg1(int n) {
    long long tid = (long long)blockIdx.x * blockDim.x + threadIdx.x;
    int node = (int)(tid >> 5);
    int lane = threadIdx.x & 31;
    if (node >= n) return;
    int beg = g_row[node];
    int end = beg + g_cnt[node];
    float4 acc = make_float4(0.f, 0.f, 0.f, 0.f);
    int p = beg;
    // unroll by 2 for MLP
    for (; p + 1 < end; p += 2) {
        int s0 = __ldg(&g_csr[p]);
        int s1 = __ldg(&g_csr[p + 1]);
        float w0 = g_deg[s0];
        float w1 = g_deg[s1];
        float4 v0 = reinterpret_cast<const float4*>(g_h1)[(size_t)s0 * 32 + lane];
        float4 v1 = reinterpret_cast<const float4*>(g_h1)[(size_t)s1 * 32 + lane];
        acc.x = fmaf(v0.x, w0, fmaf(v1.x, w1, acc.x));
        acc.y = fmaf(v0.y, w0, fmaf(v1.y, w1, acc.y));
        acc.z = fmaf(v0.z, w0, fmaf(v1.z, w1, acc.z));
        acc.w = fmaf(v0.w, w0, fmaf(v1.w, w1, acc.w));
    }
    if (p < end) {
        int s0 = __ldg(&g_csr[p]);
        float w0 = g_deg[s0];
        float4 v0 = reinterpret_cast<const float4*>(g_h1)[(size_t)s0 * 32 + lane];
        acc.x = fmaf(v0.x, w0, acc.x);
        acc.y = fmaf(v0.y, w0, acc.y);
        acc.z = fmaf(v0.z, w0, acc.z);
        acc.w = fmaf(v0.w, w0, acc.w);
    }
    float dd = g_deg[node];
    acc.x *= dd; acc.y *= dd; acc.z *= dd; acc.w *= dd;
    reinterpret_cast<float4*>(g_agg1)[(size_t)node * 32 + lane] = acc;
}

// ---------------- fused relu + bias + self-loop + GEMM2 ---------------------
__global__ void k_relu_gemm2(const float* __restrict__ b1,
                             const float* __restrict__ W2, int n) {
    __shared__ float W2s[DH * DOUT];
    __shared__ float b1s[DH];
    int t = threadIdx.x;
    for (int i = t; i < DH * DOUT; i += 256) W2s[i] = W2[i];
    if (t < DH) b1s[t] = b1[t];
    __syncthreads();

    int node = blockIdx.x * 16 + (t >> 4);
    int j = t & 15;
    if (node >= n) return;
    float di = g_deg[node];
    float dd = di * di;
    const float4* ag = reinterpret_cast<const float4*>(g_agg1 + (size_t)node * DH);
    const float4* hh = reinterpret_cast<const float4*>(g_h1 + (size_t)node * DH);
    float acc = 0.f;
#pragma unroll 8
    for (int k4 = 0; k4 < DH / 4; k4++) {
        float4 a = ag[k4];
        float4 h = hh[k4];
        float v0 = fmaxf(fmaf(h.x, dd, a.x) + b1s[k4 * 4 + 0], 0.f);
        float v1 = fmaxf(fmaf(h.y, dd, a.y) + b1s[k4 * 4 + 1], 0.f);
        float v2 = fmaxf(fmaf(h.z, dd, a.z) + b1s[k4 * 4 + 2], 0.f);
        float v3 = fmaxf(fmaf(h.w, dd, a.w) + b1s[k4 * 4 + 3], 0.f);
        acc = fmaf(v0, W2s[(k4 * 4 + 0) * DOUT + j], acc);
        acc = fmaf(v1, W2s[(k4 * 4 + 1) * DOUT + j], acc);
        acc = fmaf(v2, W2s[(k4 * 4 + 2) * DOUT + j], acc);
        acc = fmaf(v3, W2s[(k4 * 4 + 3) * DOUT + j], acc);
    }
    g_h2[(size_t)node * DOUT + j] = acc;
}

// ---------------- layer-2 aggregation: warp/node, 8 edges per iter ----------
// out[node] = b2 + dd^2 * h2[node] + dd * sum_s dinv[s] * h2[s]
__global__ void k_agg2(float* __restrict__ out, const float* __restrict__ b2, int n) {
    long long tid = (long long)blockIdx.x * blockDim.x + threadIdx.x;
    int node = (int)(tid >> 5);
    int lane = threadIdx.x & 31;
    if (node >= n) return;
    int eg = lane >> 2;      // 0..7 edge slot
    int ch = lane & 3;       // float4 chunk of the 16-dim row
    int beg = g_row[node];
    int end = beg + g_cnt[node];
    float4 acc = make_float4(0.f, 0.f, 0.f, 0.f);
    for (int p0 = beg; p0 < end; p0 += 8) {
        int p = p0 + eg;
        if (p < end) {
            int s = __ldg(&g_csr[p]);
            float w = g_deg[s];
            float4 v = reinterpret_cast<const float4*>(g_h2)[(size_t)s * 4 + ch];
            acc.x = fmaf(v.x, w, acc.x);
            acc.y = fmaf(v.y, w, acc.y);
            acc.z = fmaf(v.z, w, acc.z);
            acc.w = fmaf(v.w, w, acc.w);
        }
    }
    // reduce the 8 edge slots (lanes with equal ch, xor over bits 2..4)
#pragma unroll
    for (int m = 4; m <= 16; m <<= 1) {
        acc.x += __shfl_xor_sync(0xffffffffu, acc.x, m);
        acc.y += __shfl_xor_sync(0xffffffffu, acc.y, m);
        acc.z += __shfl_xor_sync(0xffffffffu, acc.z, m);
        acc.w += __shfl_xor_sync(0xffffffffu, acc.w, m);
    }
    if (lane < 4) {
        float di = g_deg[node];
        float dd = di * di;
        float4 bb = reinterpret_cast<const float4*>(b2)[lane];
        float4 hv = reinterpret_cast<const float4*>(g_h2)[(size_t)node * 4 + lane];
        float4 o;
        o.x = bb.x + fmaf(hv.x, dd, acc.x * di);
        o.y = bb.y + fmaf(hv.y, dd, acc.y * di);
        o.z = bb.z + fmaf(hv.z, dd, acc.z * di);
        o.w = bb.w + fmaf(hv.w, dd, acc.w * di);
        reinterpret_cast<float4*>(out)[(size_t)node * 4 + lane] = o;
    }
}

// ---------------- launch -----------------------------------------------------
extern "C" void kernel_launch(void* const* d_in, const int* in_sizes, int n_in,
                              void* d_out, int out_size) {
    const float* x  = (const float*)d_in[0];
    const void*  ei = d_in[1];                  // [2,E], int64 OR int32 (detected)
    const float* W1 = (const float*)d_in[2];
    const float* b1 = (const float*)d_in[3];
    const float* W2 = (const float*)d_in[4];
    const float* b2 = (const float*)d_in[5];
    float* out = (float*)d_out;

    int n = in_sizes[0] / DIN;
    int e = in_sizes[1] / 2;

    k_detect<<<1, 1>>>(ei);
    int m = (e > n) ? e : n;
    k_convert<<<(m + 255) / 256, 256>>>(ei, e, n);
    k_count<<<(e + 255) / 256, 256>>>(e);

    int nb = (n + 1023) / 1024;                 // <= 98
    k_scan1<<<nb, 256>>>(n);
    k_scan2<<<1, 128>>>(nb);
    k_scan3<<<(n + 255) / 256, 256>>>(n);
    k_fill<<<(e + 255) / 256, 256>>>(e);

    int smem = (DIN * DH + GTM * DIN) * (int)sizeof(float);   // 96 KB
    cudaFuncSetAttribute(k_gemm1, cudaFuncAttributeMaxDynamicSharedMemorySize, smem);
    k_gemm1<<<(n + GTM - 1) / GTM, 256, smem>>>(x, W1, n);

    long long thr = (long long)n * 32;
    k_agg1<<<(unsigned)((thr + 255) / 256), 256>>>(n);
    k_relu_gemm2<<<(n + 15) / 16, 256>>>(b1, W2, n);
    k_agg2<<<(unsigned)((thr + 255) / 256), 256>>>(out, b2, n);
}

// round 9
// speedup vs baseline: 2.2211x; 1.1555x over previous
#include <cuda_runtime.h>
#include <cuda_fp16.h>
#include <cstdint>

#define NMAX   100000
#define EMAX   1600000
#define DIN    128
#define DH     128
#define DOUT   16

// ---------------- device scratch --------------------------------------------
__device__ __align__(16) float g_deg[NMAX];                 // dinv = rsqrt(deg+1)
__device__ __align__(16) float g_h1[(size_t)NMAX * DH];     // x @ W1 (fp32)
__device__ __align__(16) uint2 g_h1h[(size_t)NMAX * 32];    // x @ W1 (half2 pairs)
__device__ __align__(16) float g_agg1[(size_t)NMAX * DH];   // edge agg, layer 1
__device__ __align__(16) float g_h2[(size_t)NMAX * DOUT];   // relu(...) @ W2
__device__ int g_csr[EMAX];
__device__ int g_cnt[NMAX];
__device__ int g_row[NMAX];
__device__ int g_cur[NMAX];
__device__ int g_excl[NMAX];
__device__ int g_bsum[128];
__device__ int g_is64;

// ---------------- helpers ---------------------------------------------------
__device__ __forceinline__ int load_idx(const void* __restrict__ ei, long long i) {
    if (g_is64) return (int)__ldg(((const long long*)ei) + i);
    return __ldg(((const int*)ei) + i);
}
// packed fp32x2 FMA (FFMA2): d = a*b + d, per-lane IEEE fp32
__device__ __forceinline__ void ffma2(unsigned long long& d,
                                      unsigned long long a, unsigned long long b) {
    asm("fma.rn.f32x2 %0, %1, %2, %0;" : "+l"(d) : "l"(a), "l"(b));
}
__device__ __forceinline__ unsigned long long pack2(float lo, float hi) {
    unsigned long long r;
    asm("mov.b64 %0, {%1, %2};" : "=l"(r) : "f"(lo), "f"(hi));
    return r;
}
__device__ __forceinline__ float2 unpack2(unsigned long long v) {
    float lo, hi;
    asm("mov.b64 {%0, %1}, %2;" : "=f"(lo), "=f"(hi) : "l"(v));
    return make_float2(lo, hi);
}

// ---------------- CSR construction ------------------------------------------
// zero histogram + detect edge_index dtype (indices<100000 -> true int64 has
// zero high words; int32 data aliases a random index into the high word)
__global__ void k_init(const void* __restrict__ ei, int n) {
    int i = blockIdx.x * blockDim.x + threadIdx.x;
    if (i < n) g_cnt[i] = 0;
    if (i == 0) {
        const unsigned long long* p = (const unsigned long long*)ei;
        int is64 = 1;
        for (int k = 0; k < 64; k++)
            if ((p[k] >> 32) != 0ull) { is64 = 0; break; }
        g_is64 = is64;
    }
}

__global__ void k_count(const void* __restrict__ ei, int e) {
    int i = blockIdx.x * blockDim.x + threadIdx.x;
    if (i < e) atomicAdd(&g_cnt[load_idx(ei, (long long)e + i)], 1);
}

__global__ void k_scan1(int n) {
    __shared__ int sh[256];
    int t = threadIdx.x;
    int base = blockIdx.x * 1024;
    int v[4], s = 0;
#pragma unroll
    for (int i = 0; i < 4; i++) {
        int idx = base + t * 4 + i;
        v[i] = (idx < n) ? g_cnt[idx] : 0;
        s += v[i];
    }
    sh[t] = s;
    __syncthreads();
    int own = s;
    for (int off = 1; off < 256; off <<= 1) {
        int o = (t >= off) ? sh[t - off] : 0;
        __syncthreads();
        sh[t] += o;
        __syncthreads();
    }
    if (t == 255) g_bsum[blockIdx.x] = sh[255];
    int run = sh[t] - own;
#pragma unroll
    for (int i = 0; i < 4; i++) {
        int idx = base + t * 4 + i;
        if (idx < n) g_excl[idx] = run;
        run += v[i];
    }
}

__global__ void k_scan2(int nb) {
    __shared__ int sh[128];
    int t = threadIdx.x;
    int v = (t < nb) ? g_bsum[t] : 0;
    sh[t] = v;
    __syncthreads();
    for (int off = 1; off < 128; off <<= 1) {
        int o = (t >= off) ? sh[t - off] : 0;
        __syncthreads();
        sh[t] += o;
        __syncthreads();
    }
    if (t < nb) g_bsum[t] = sh[t] - v;
}

__global__ void k_scan3(int n) {
    int i = blockIdx.x * blockDim.x + threadIdx.x;
    if (i < n) {
        int r = g_excl[i] + g_bsum[i >> 10];
        g_row[i] = r;
        g_cur[i] = r;
        g_deg[i] = rsqrtf((float)g_cnt[i] + 1.0f);
    }
}

__global__ void k_fill(const void* __restrict__ ei, int e) {
    int i = blockIdx.x * blockDim.x + threadIdx.x;
    if (i < e) {
        int s = load_idx(ei, i);
        int d = load_idx(ei, (long long)e + i);
        int pos = atomicAdd(&g_cur[d], 1);
        g_csr[pos] = s;
    }
}

// ---------------- GEMM1: h1 = x @ W1 (FFMA2 packed fp32) --------------------
// 64x128 tile per block, 256 threads, each thread 8 rows x 4 cols.
// Accumulators live as f32x2 pairs; fma.rn.f32x2 halves fma-pipe pressure.
#define GTM 64
__global__ void k_gemm1(const float* __restrict__ x,
                        const float* __restrict__ W1, int n) {
    extern __shared__ float sm[];
    float* Ws = sm;                 // 128*128
    float* Xs = sm + DIN * DH;      // GTM*128
    int t = threadIdx.x;

    for (int i = t; i < DIN * DH / 4; i += 256)
        reinterpret_cast<float4*>(Ws)[i] = reinterpret_cast<const float4*>(W1)[i];

    int row0 = blockIdx.x * GTM;
    for (int i = t; i < GTM * DIN / 4; i += 256) {
        int r = i >> 5, c4 = i & 31;
        int gr = row0 + r;
        float4 v = make_float4(0.f, 0.f, 0.f, 0.f);
        if (gr < n) v = reinterpret_cast<const float4*>(x)[(size_t)gr * 32 + c4];
        reinterpret_cast<float4*>(Xs)[i] = v;
    }
    __syncthreads();

    int cx = t & 31;
    int ry = t >> 5;
    unsigned long long acc01[8], acc23[8];
#pragma unroll
    for (int r = 0; r < 8; r++) { acc01[r] = 0ull; acc23[r] = 0ull; }

#pragma unroll 4
    for (int k = 0; k < DIN; k++) {
        float4 w = reinterpret_cast<const float4*>(Ws)[k * 32 + cx];
        unsigned long long w01 = pack2(w.x, w.y);
        unsigned long long w23 = pack2(w.z, w.w);
#pragma unroll
        for (int r = 0; r < 8; r++) {
            float a = Xs[(ry * 8 + r) * DIN + k];   // warp-uniform broadcast
            unsigned long long aa = pack2(a, a);
            ffma2(acc01[r], aa, w01);
            ffma2(acc23[r], aa, w23);
        }
    }
#pragma unroll
    for (int r = 0; r < 8; r++) {
        int gr = row0 + ry * 8 + r;
        if (gr < n) {
            float2 p0 = unpack2(acc01[r]);
            float2 p1 = unpack2(acc23[r]);
            reinterpret_cast<float4*>(g_h1)[(size_t)gr * 32 + cx] =
                make_float4(p0.x, p0.y, p1.x, p1.y);
            __half2 h0 = __floats2half2_rn(p0.x, p0.y);
            __half2 h1 = __floats2half2_rn(p1.x, p1.y);
            uint2 u;
            u.x = *reinterpret_cast<uint32_t*>(&h0);
            u.y = *reinterpret_cast<uint32_t*>(&h1);
            g_h1h[(size_t)gr * 32 + cx] = u;
        }
    }
}

// ---------------- layer-1 aggregation: warp/node, fp16 gather, fp32 accum ---
__global__ void k_agg1(int n) {
    long long tid = (long long)blockIdx.x * blockDim.x + threadIdx.x;
    int node = (int)(tid >> 5);
    int lane = threadIdx.x & 31;
    if (node >= n) return;
    int beg = g_row[node];
    int end = beg + g_cnt[node];
    float4 acc = make_float4(0.f, 0.f, 0.f, 0.f);
    int p = beg;
    for (; p + 3 < end; p += 4) {
        int s0 = __ldg(&g_csr[p]),     s1 = __ldg(&g_csr[p + 1]);
        int s2 = __ldg(&g_csr[p + 2]), s3 = __ldg(&g_csr[p + 3]);
        float w0 = g_deg[s0], w1 = g_deg[s1], w2 = g_deg[s2], w3 = g_deg[s3];
        uint2 u0 = g_h1h[(size_t)s0 * 32 + lane];
        uint2 u1 = g_h1h[(size_t)s1 * 32 + lane];
        uint2 u2 = g_h1h[(size_t)s2 * 32 + lane];
        uint2 u3 = g_h1h[(size_t)s3 * 32 + lane];
        float2 a0 = __half22float2(*reinterpret_cast<__half2*>(&u0.x));
        float2 b0 = __half22float2(*reinterpret_cast<__half2*>(&u0.y));
        float2 a1 = __half22float2(*reinterpret_cast<__half2*>(&u1.x));
        float2 b1 = __half22float2(*reinterpret_cast<__half2*>(&u1.y));
        float2 a2 = __half22float2(*reinterpret_cast<__half2*>(&u2.x));
        float2 b2 = __half22float2(*reinterpret_cast<__half2*>(&u2.y));
        float2 a3 = __half22float2(*reinterpret_cast<__half2*>(&u3.x));
        float2 b3 = __half22float2(*reinterpret_cast<__half2*>(&u3.y));
        acc.x += a0.x * w0 + a1.x * w1 + a2.x * w2 + a3.x * w3;
        acc.y += a0.y * w0 + a1.y * w1 + a2.y * w2 + a3.y * w3;
        acc.z += b0.x * w0 + b1.x * w1 + b2.x * w2 + b3.x * w3;
        acc.w += b0.y * w0 + b1.y * w1 + b2.y * w2 + b3.y * w3;
    }
    for (; p < end; p++) {
        int s0 = __ldg(&g_csr[p]);
        float w0 = g_deg[s0];
        uint2 u0 = g_h1h[(size_t)s0 * 32 + lane];
        float2 a0 = __half22float2(*reinterpret_cast<__half2*>(&u0.x));
        float2 b0 = __half22float2(*reinterpret_cast<__half2*>(&u0.y));
        acc.x = fmaf(a0.x, w0, acc.x);
        acc.y = fmaf(a0.y, w0, acc.y);
        acc.z = fmaf(b0.x, w0, acc.z);
        acc.w = fmaf(b0.y, w0, acc.w);
    }
    float dd = g_deg[node];
    acc.x *= dd; acc.y *= dd; acc.z *= dd; acc.w *= dd;
    reinterpret_cast<float4*>(g_agg1)[(size_t)node * 32 + lane] = acc;
}

// ---------------- fused relu + bias + self-loop + GEMM2 ---------------------
__global__ void k_relu_gemm2(const float* __restrict__ b1,
                             const float* __restrict__ W2, int n) {
    __shared__ float W2s[DH * DOUT];
    __shared__ float b1s[DH];
    int t = threadIdx.x;
    for (int i = t; i < DH * DOUT; i += 256) W2s[i] = W2[i];
    if (t < DH) b1s[t] = b1[t];
    __syncthreads();

    int node = blockIdx.x * 16 + (t >> 4);
    int j = t & 15;
    if (node >= n) return;
    float di = g_deg[node];
    float dd = di * di;
    const float4* ag = reinterpret_cast<const float4*>(g_agg1 + (size_t)node * DH);
    const float4* hh = reinterpret_cast<const float4*>(g_h1 + (size_t)node * DH);
    float acc = 0.f;
#pragma unroll 8
    for (int k4 = 0; k4 < DH / 4; k4++) {
        float4 a = ag[k4];
        float4 h = hh[k4];
        float v0 = fmaxf(fmaf(h.x, dd, a.x) + b1s[k4 * 4 + 0], 0.f);
        float v1 = fmaxf(fmaf(h.y, dd, a.y) + b1s[k4 * 4 + 1], 0.f);
        float v2 = fmaxf(fmaf(h.z, dd, a.z) + b1s[k4 * 4 + 2], 0.f);
        float v3 = fmaxf(fmaf(h.w, dd, a.w) + b1s[k4 * 4 + 3], 0.f);
        acc = fmaf(v0, W2s[(k4 * 4 + 0) * DOUT + j], acc);
        acc = fmaf(v1, W2s[(k4 * 4 + 1) * DOUT + j], acc);
        acc = fmaf(v2, W2s[(k4 * 4 + 2) * DOUT + j], acc);
        acc = fmaf(v3, W2s[(k4 * 4 + 3) * DOUT + j], acc);
    }
    g_h2[(size_t)node * DOUT + j] = acc;
}

// ---------------- layer-2 aggregation ---------------------------------------
__global__ void k_agg2(float* __restrict__ out, const float* __restrict__ b2, int n) {
    long long tid = (long long)blockIdx.x * blockDim.x + threadIdx.x;
    int node = (int)(tid >> 5);
    int lane = threadIdx.x & 31;
    if (node >= n) return;
    int eg = lane >> 2;
    int ch = lane & 3;
    int beg = g_row[node];
    int end = beg + g_cnt[node];
    float4 acc = make_float4(0.f, 0.f, 0.f, 0.f);
    for (int p0 = beg; p0 < end; p0 += 8) {
        int p = p0 + eg;
        if (p < end) {
            int s = __ldg(&g_csr[p]);
            float w = g_deg[s];
            float4 v = reinterpret_cast<const float4*>(g_h2)[(size_t)s * 4 + ch];
            acc.x = fmaf(v.x, w, acc.x);
            acc.y = fmaf(v.y, w, acc.y);
            acc.z = fmaf(v.z, w, acc.z);
            acc.w = fmaf(v.w, w, acc.w);
        }
    }
#pragma unroll
    for (int m = 4; m <= 16; m <<= 1) {
        acc.x += __shfl_xor_sync(0xffffffffu, acc.x, m);
        acc.y += __shfl_xor_sync(0xffffffffu, acc.y, m);
        acc.z += __shfl_xor_sync(0xffffffffu, acc.z, m);
        acc.w += __shfl_xor_sync(0xffffffffu, acc.w, m);
    }
    if (lane < 4) {
        float di = g_deg[node];
        float dd = di * di;
        float4 bb = reinterpret_cast<const float4*>(b2)[lane];
        float4 hv = reinterpret_cast<const float4*>(g_h2)[(size_t)node * 4 + lane];
        float4 o;
        o.x = bb.x + fmaf(hv.x, dd, acc.x * di);
        o.y = bb.y + fmaf(hv.y, dd, acc.y * di);
        o.z = bb.z + fmaf(hv.z, dd, acc.z * di);
        o.w = bb.w + fmaf(hv.w, dd, acc.w * di);
        reinterpret_cast<float4*>(out)[(size_t)node * 4 + lane] = o;
    }
}

// ---------------- launch -----------------------------------------------------
extern "C" void kernel_launch(void* const* d_in, const int* in_sizes, int n_in,
                              void* d_out, int out_size) {
    const float* x  = (const float*)d_in[0];
    const void*  ei = d_in[1];                  // [2,E], int64 or int32 (detected)
    const float* W1 = (const float*)d_in[2];
    const float* b1 = (const float*)d_in[3];
    const float* W2 = (const float*)d_in[4];
    const float* b2 = (const float*)d_in[5];
    float* out = (float*)d_out;

    int n = in_sizes[0] / DIN;
    int e = in_sizes[1] / 2;

    k_init<<<(n + 255) / 256, 256>>>(ei, n);
    k_count<<<(e + 255) / 256, 256>>>(ei, e);

    int nb = (n + 1023) / 1024;
    k_scan1<<<nb, 256>>>(n);
    k_scan2<<<1, 128>>>(nb);
    k_scan3<<<(n + 255) / 256, 256>>>(n);
    k_fill<<<(e + 255) / 256, 256>>>(ei, e);

    int smem = (DIN * DH + GTM * DIN) * (int)sizeof(float);   // 96 KB
    cudaFuncSetAttribute(k_gemm1, cudaFuncAttributeMaxDynamicSharedMemorySize, smem);
    k_gemm1<<<(n + GTM - 1) / GTM, 256, smem>>>(x, W1, n);

    long long thr = (long long)n * 32;
    k_agg1<<<(unsigned)((thr + 255) / 256), 256>>>(n);
    k_relu_gemm2<<<(n + 15) / 16, 256>>>(b1, W2, n);
    k_agg2<<<(unsigned)((thr + 255) / 256), 256>>>(out, b2, n);
}

// round 10
// speedup vs baseline: 2.4534x; 1.1046x over previous
#include <cuda_runtime.h>
#include <cuda_fp16.h>
#include <cstdint>

#define NMAX   100000
#define EMAX   1600000
#define DIN    128
#define DH     128
#define DOUT   16

// ---------------- device scratch --------------------------------------------
__device__ __align__(16) float g_deg[NMAX];                 // dinv = rsqrt(deg+1)
__device__ __align__(16) uint2 g_h1h[(size_t)NMAX * 32];    // x @ W1 (half2 pairs)
__device__ __align__(16) float g_agg1[(size_t)NMAX * DH];   // edge agg, layer 1
__device__ __align__(16) float g_h2[(size_t)NMAX * DOUT];   // relu(...) @ W2 fp32
__device__ __align__(16) uint2 g_h2h[(size_t)NMAX * 2];     // same, half2 x4 per row half... 16 halves = 2x uint2? (16 halves = 32B = 2 uint2x... actually 4 uint2) 
__device__ __align__(16) uint4 g_h2h4[(size_t)NMAX];        // 16 halves = 32B? no: uint4=16B=8 halves. use 2 per row
__device__ __align__(16) uint4 g_h2hx[(size_t)NMAX * 2];    // 16 halves = 2 x uint4
__device__ int g_csr[EMAX];
__device__ int g_cnt[NMAX];
__device__ int g_row[NMAX];
__device__ int g_cur[NMAX];
__device__ int g_excl[NMAX];
__device__ int g_bsum[128];
__device__ int g_is64;

// ---------------- helpers ---------------------------------------------------
__device__ __forceinline__ int load_idx(const void* __restrict__ ei, long long i) {
    if (g_is64) return (int)__ldg(((const long long*)ei) + i);
    return __ldg(((const int*)ei) + i);
}
__device__ __forceinline__ void ffma2(unsigned long long& d,
                                      unsigned long long a, unsigned long long b) {
    asm("fma.rn.f32x2 %0, %1, %2, %0;" : "+l"(d) : "l"(a), "l"(b));
}
__device__ __forceinline__ unsigned long long pack2(float lo, float hi) {
    unsigned long long r;
    asm("mov.b64 %0, {%1, %2};" : "=l"(r) : "f"(lo), "f"(hi));
    return r;
}
__device__ __forceinline__ float2 unpack2(unsigned long long v) {
    float lo, hi;
    asm("mov.b64 {%0, %1}, %2;" : "=f"(lo), "=f"(hi) : "l"(v));
    return make_float2(lo, hi);
}
__device__ __forceinline__ float2 h2f2(uint32_t u) {
    return __half22float2(*reinterpret_cast<__half2*>(&u));
}

// ---------------- CSR construction ------------------------------------------
__global__ void k_init(const void* __restrict__ ei, int n) {
    int i = blockIdx.x * blockDim.x + threadIdx.x;
    if (i < n) g_cnt[i] = 0;
    if (i == 0) {
        const unsigned long long* p = (const unsigned long long*)ei;
        int is64 = 1;
        for (int k = 0; k < 64; k++)
            if ((p[k] >> 32) != 0ull) { is64 = 0; break; }
        g_is64 = is64;
    }
}

__global__ void k_count(const void* __restrict__ ei, int e) {
    int i = blockIdx.x * blockDim.x + threadIdx.x;
    if (i < e) atomicAdd(&g_cnt[load_idx(ei, (long long)e + i)], 1);
}

__global__ void k_scan1(int n) {
    __shared__ int sh[256];
    int t = threadIdx.x;
    int base = blockIdx.x * 1024;
    int v[4], s = 0;
#pragma unroll
    for (int i = 0; i < 4; i++) {
        int idx = base + t * 4 + i;
        v[i] = (idx < n) ? g_cnt[idx] : 0;
        s += v[i];
    }
    sh[t] = s;
    __syncthreads();
    int own = s;
    for (int off = 1; off < 256; off <<= 1) {
        int o = (t >= off) ? sh[t - off] : 0;
        __syncthreads();
        sh[t] += o;
        __syncthreads();
    }
    if (t == 255) g_bsum[blockIdx.x] = sh[255];
    int run = sh[t] - own;
#pragma unroll
    for (int i = 0; i < 4; i++) {
        int idx = base + t * 4 + i;
        if (idx < n) g_excl[idx] = run;
        run += v[i];
    }
}

__global__ void k_scan2(int nb) {
    __shared__ int sh[128];
    int t = threadIdx.x;
    int v = (t < nb) ? g_bsum[t] : 0;
    sh[t] = v;
    __syncthreads();
    for (int off = 1; off < 128; off <<= 1) {
        int o = (t >= off) ? sh[t - off] : 0;
        __syncthreads();
        sh[t] += o;
        __syncthreads();
    }
    if (t < nb) g_bsum[t] = sh[t] - v;
}

__global__ void k_scan3(int n) {
    int i = blockIdx.x * blockDim.x + threadIdx.x;
    if (i < n) {
        int r = g_excl[i] + g_bsum[i >> 10];
        g_row[i] = r;
        g_cur[i] = r;
        g_deg[i] = rsqrtf((float)g_cnt[i] + 1.0f);
    }
}

__global__ void k_fill(const void* __restrict__ ei, int e) {
    int i = blockIdx.x * blockDim.x + threadIdx.x;
    if (i < e) {
        int s = load_idx(ei, i);
        int d = load_idx(ei, (long long)e + i);
        int pos = atomicAdd(&g_cur[d], 1);
        g_csr[pos] = s;
    }
}

// ---------------- GEMM1: h1h = fp16(x @ W1)  (FFMA2 packed fp32) ------------
#define GTM 64
__global__ void k_gemm1(const float* __restrict__ x,
                        const float* __restrict__ W1, int n) {
    extern __shared__ float sm[];
    float* Ws = sm;                 // 128*128
    float* Xs = sm + DIN * DH;      // GTM*128
    int t = threadIdx.x;

    for (int i = t; i < DIN * DH / 4; i += 256)
        reinterpret_cast<float4*>(Ws)[i] = reinterpret_cast<const float4*>(W1)[i];

    int row0 = blockIdx.x * GTM;
    for (int i = t; i < GTM * DIN / 4; i += 256) {
        int r = i >> 5, c4 = i & 31;
        int gr = row0 + r;
        float4 v = make_float4(0.f, 0.f, 0.f, 0.f);
        if (gr < n) v = reinterpret_cast<const float4*>(x)[(size_t)gr * 32 + c4];
        reinterpret_cast<float4*>(Xs)[i] = v;
    }
    __syncthreads();

    int cx = t & 31;
    int ry = t >> 5;
    unsigned long long acc01[8], acc23[8];
#pragma unroll
    for (int r = 0; r < 8; r++) { acc01[r] = 0ull; acc23[r] = 0ull; }

#pragma unroll 4
    for (int k = 0; k < DIN; k++) {
        float4 w = reinterpret_cast<const float4*>(Ws)[k * 32 + cx];
        unsigned long long w01 = pack2(w.x, w.y);
        unsigned long long w23 = pack2(w.z, w.w);
#pragma unroll
        for (int r = 0; r < 8; r++) {
            float a = Xs[(ry * 8 + r) * DIN + k];
            unsigned long long aa = pack2(a, a);
            ffma2(acc01[r], aa, w01);
            ffma2(acc23[r], aa, w23);
        }
    }
#pragma unroll
    for (int r = 0; r < 8; r++) {
        int gr = row0 + ry * 8 + r;
        if (gr < n) {
            float2 p0 = unpack2(acc01[r]);
            float2 p1 = unpack2(acc23[r]);
            __half2 h0 = __floats2half2_rn(p0.x, p0.y);
            __half2 h1 = __floats2half2_rn(p1.x, p1.y);
            uint2 u;
            u.x = *reinterpret_cast<uint32_t*>(&h0);
            u.y = *reinterpret_cast<uint32_t*>(&h1);
            g_h1h[(size_t)gr * 32 + cx] = u;
        }
    }
}

// ---------------- layer-1 aggregation: warp/node, fp16 gather, fp32 accum ---
__global__ void k_agg1(int n) {
    long long tid = (long long)blockIdx.x * blockDim.x + threadIdx.x;
    int node = (int)(tid >> 5);
    int lane = threadIdx.x & 31;
    if (node >= n) return;
    int beg = g_row[node];
    int end = beg + g_cnt[node];
    float4 acc = make_float4(0.f, 0.f, 0.f, 0.f);
    int p = beg;
    for (; p + 3 < end; p += 4) {
        int s0 = __ldg(&g_csr[p]),     s1 = __ldg(&g_csr[p + 1]);
        int s2 = __ldg(&g_csr[p + 2]), s3 = __ldg(&g_csr[p + 3]);
        float w0 = g_deg[s0], w1 = g_deg[s1], w2 = g_deg[s2], w3 = g_deg[s3];
        uint2 u0 = g_h1h[(size_t)s0 * 32 + lane];
        uint2 u1 = g_h1h[(size_t)s1 * 32 + lane];
        uint2 u2 = g_h1h[(size_t)s2 * 32 + lane];
        uint2 u3 = g_h1h[(size_t)s3 * 32 + lane];
        float2 a0 = h2f2(u0.x), b0 = h2f2(u0.y);
        float2 a1 = h2f2(u1.x), b1 = h2f2(u1.y);
        float2 a2 = h2f2(u2.x), b2 = h2f2(u2.y);
        float2 a3 = h2f2(u3.x), b3 = h2f2(u3.y);
        acc.x += a0.x * w0 + a1.x * w1 + a2.x * w2 + a3.x * w3;
        acc.y += a0.y * w0 + a1.y * w1 + a2.y * w2 + a3.y * w3;
        acc.z += b0.x * w0 + b1.x * w1 + b2.x * w2 + b3.x * w3;
        acc.w += b0.y * w0 + b1.y * w1 + b2.y * w2 + b3.y * w3;
    }
    for (; p < end; p++) {
        int s0 = __ldg(&g_csr[p]);
        float w0 = g_deg[s0];
        uint2 u0 = g_h1h[(size_t)s0 * 32 + lane];
        float2 a0 = h2f2(u0.x), b0 = h2f2(u0.y);
        acc.x = fmaf(a0.x, w0, acc.x);
        acc.y = fmaf(a0.y, w0, acc.y);
        acc.z = fmaf(b0.x, w0, acc.z);
        acc.w = fmaf(b0.y, w0, acc.w);
    }
    float dd = g_deg[node];
    acc.x *= dd; acc.y *= dd; acc.z *= dd; acc.w *= dd;
    reinterpret_cast<float4*>(g_agg1)[(size_t)node * 32 + lane] = acc;
}

// ---------------- fused relu + bias + self-loop + GEMM2 ---------------------
// self term from fp16 h1h; emits h2 fp32 (for agg2 self) + h2hx fp16 (gather)
__global__ void k_relu_gemm2(const float* __restrict__ b1,
                             const float* __restrict__ W2, int n) {
    __shared__ float W2s[DH * DOUT];
    __shared__ float b1s[DH];
    int t = threadIdx.x;
    for (int i = t; i < DH * DOUT; i += 256) W2s[i] = W2[i];
    if (t < DH) b1s[t] = b1[t];
    __syncthreads();

    int node = blockIdx.x * 16 + (t >> 4);
    int j = t & 15;
    if (node >= n) return;
    float di = g_deg[node];
    float dd = di * di;
    const float4* ag = reinterpret_cast<const float4*>(g_agg1 + (size_t)node * DH);
    const uint2*  hh = g_h1h + (size_t)node * 32;
    float acc = 0.f;
#pragma unroll 8
    for (int k4 = 0; k4 < DH / 4; k4++) {
        float4 a = ag[k4];
        uint2  u = hh[k4];
        float2 h0 = h2f2(u.x), h1 = h2f2(u.y);
        float v0 = fmaxf(fmaf(h0.x, dd, a.x) + b1s[k4 * 4 + 0], 0.f);
        float v1 = fmaxf(fmaf(h0.y, dd, a.y) + b1s[k4 * 4 + 1], 0.f);
        float v2 = fmaxf(fmaf(h1.x, dd, a.z) + b1s[k4 * 4 + 2], 0.f);
        float v3 = fmaxf(fmaf(h1.y, dd, a.w) + b1s[k4 * 4 + 3], 0.f);
        acc = fmaf(v0, W2s[(k4 * 4 + 0) * DOUT + j], acc);
        acc = fmaf(v1, W2s[(k4 * 4 + 1) * DOUT + j], acc);
        acc = fmaf(v2, W2s[(k4 * 4 + 2) * DOUT + j], acc);
        acc = fmaf(v3, W2s[(k4 * 4 + 3) * DOUT + j], acc);
    }
    g_h2[(size_t)node * DOUT + j] = acc;
    // fp16 copy: threads j and j+1 pair up via shfl to form half2
    float nb = __shfl_xor_sync(0xffffffffu, acc, 1);
    if ((j & 1) == 0) {
        __half2 hp = __floats2half2_rn(acc, nb);
        ((uint32_t*)g_h2hx)[(size_t)node * 8 + (j >> 1)] = *reinterpret_cast<uint32_t*>(&hp);
    }
}

// ---------------- layer-2 aggregation (fp16 gather) -------------------------
__global__ void k_agg2(float* __restrict__ out, const float* __restrict__ b2, int n) {
    long long tid = (long long)blockIdx.x * blockDim.x + threadIdx.x;
    int node = (int)(tid >> 5);
    int lane = threadIdx.x & 31;
    if (node >= n) return;
    int eg = lane >> 1;        // 0..15 edge slot
    int ch = lane & 1;         // uint4 half (8 halves = 8 features)
    int beg = g_row[node];
    int end = beg + g_cnt[node];
    float4 acc = make_float4(0.f, 0.f, 0.f, 0.f);
    float4 acc2 = make_float4(0.f, 0.f, 0.f, 0.f);
    for (int p0 = beg; p0 < end; p0 += 16) {
        int p = p0 + eg;
        if (p < end) {
            int s = __ldg(&g_csr[p]);
            float w = g_deg[s];
            uint4 u = g_h2hx[(size_t)s * 2 + ch];
            float2 f0 = h2f2(u.x), f1 = h2f2(u.y), f2 = h2f2(u.z), f3 = h2f2(u.w);
            acc.x  = fmaf(f0.x, w, acc.x);
            acc.y  = fmaf(f0.y, w, acc.y);
            acc.z  = fmaf(f1.x, w, acc.z);
            acc.w  = fmaf(f1.y, w, acc.w);
            acc2.x = fmaf(f2.x, w, acc2.x);
            acc2.y = fmaf(f2.y, w, acc2.y);
            acc2.z = fmaf(f3.x, w, acc2.z);
            acc2.w = fmaf(f3.y, w, acc2.w);
        }
    }
    // reduce the 16 edge slots: lanes with same ch differ in bits 1..4
#pragma unroll
    for (int m = 2; m <= 16; m <<= 1) {
        acc.x  += __shfl_xor_sync(0xffffffffu, acc.x,  m);
        acc.y  += __shfl_xor_sync(0xffffffffu, acc.y,  m);
        acc.z  += __shfl_xor_sync(0xffffffffu, acc.z,  m);
        acc.w  += __shfl_xor_sync(0xffffffffu, acc.w,  m);
        acc2.x += __shfl_xor_sync(0xffffffffu, acc2.x, m);
        acc2.y += __shfl_xor_sync(0xffffffffu, acc2.y, m);
        acc2.z += __shfl_xor_sync(0xffffffffu, acc2.z, m);
        acc2.w += __shfl_xor_sync(0xffffffffu, acc2.w, m);
    }
    if (lane < 2) {
        float di = g_deg[node];
        float dd = di * di;
        // lane ch handles features ch*8 .. ch*8+7 -> two float4 chunks
        int c0 = lane * 2;          // float4 chunk index (0,1) or (2,3)
        float4 bb0 = reinterpret_cast<const float4*>(b2)[c0];
        float4 bb1 = reinterpret_cast<const float4*>(b2)[c0 + 1];
        float4 hv0 = reinterpret_cast<const float4*>(g_h2)[(size_t)node * 4 + c0];
        float4 hv1 = reinterpret_cast<const float4*>(g_h2)[(size_t)node * 4 + c0 + 1];
        float4 o0, o1;
        o0.x = bb0.x + fmaf(hv0.x, dd, acc.x  * di);
        o0.y = bb0.y + fmaf(hv0.y, dd, acc.y  * di);
        o0.z = bb0.z + fmaf(hv0.z, dd, acc.z  * di);
        o0.w = bb0.w + fmaf(hv0.w, dd, acc.w  * di);
        o1.x = bb1.x + fmaf(hv1.x, dd, acc2.x * di);
        o1.y = bb1.y + fmaf(hv1.y, dd, acc2.y * di);
        o1.z = bb1.z + fmaf(hv1.z, dd, acc2.z * di);
        o1.w = bb1.w + fmaf(hv1.w, dd, acc2.w * di);
        reinterpret_cast<float4*>(out)[(size_t)node * 4 + c0]     = o0;
        reinterpret_cast<float4*>(out)[(size_t)node * 4 + c0 + 1] = o1;
    }
}

// ---------------- launch -----------------------------------------------------
extern "C" void kernel_launch(void* const* d_in, const int* in_sizes, int n_in,
                              void* d_out, int out_size) {
    const float* x  = (const float*)d_in[0];
    const void*  ei = d_in[1];
    const float* W1 = (const float*)d_in[2];
    const float* b1 = (const float*)d_in[3];
    const float* W2 = (const float*)d_in[4];
    const float* b2 = (const float*)d_in[5];
    float* out = (float*)d_out;

    int n = in_sizes[0] / DIN;
    int e = in_sizes[1] / 2;

    // one-time fork/join plumbing (host handles only; no device memory)
    static cudaStream_t s2 = 0;
    static cudaEvent_t evA = 0, evB = 0;
    static int tried = 0;
    if (!tried) {
        tried = 1;
        if (cudaStreamCreateWithFlags(&s2, cudaStreamNonBlocking) != cudaSuccess) s2 = 0;
        if (s2) {
            if (cudaEventCreateWithFlags(&evA, cudaEventDisableTiming) != cudaSuccess ||
                cudaEventCreateWithFlags(&evB, cudaEventDisableTiming) != cudaSuccess) {
                s2 = 0;
            }
        }
    }
    cudaStream_t sc = s2 ? s2 : 0;   // CSR chain stream

    if (s2) {
        cudaEventRecord(evA, 0);
        cudaStreamWaitEvent(s2, evA, 0);
    }

    // CSR build (stream sc) — independent of gemm1
    k_init<<<(n + 255) / 256, 256, 0, sc>>>(ei, n);
    k_count<<<(e + 255) / 256, 256, 0, sc>>>(ei, e);
    int nb = (n + 1023) / 1024;
    k_scan1<<<nb, 256, 0, sc>>>(n);
    k_scan2<<<1, 128, 0, sc>>>(nb);
    k_scan3<<<(n + 255) / 256, 256, 0, sc>>>(n);
    k_fill<<<(e + 255) / 256, 256, 0, sc>>>(ei, e);

    // GEMM1 (default stream, concurrent with CSR build)
    int smem = (DIN * DH + GTM * DIN) * (int)sizeof(float);   // 96 KB
    cudaFuncSetAttribute(k_gemm1, cudaFuncAttributeMaxDynamicSharedMemorySize, smem);
    k_gemm1<<<(n + GTM - 1) / GTM, 256, smem>>>(x, W1, n);

    if (s2) {
        cudaEventRecord(evB, s2);
        cudaStreamWaitEvent(0, evB, 0);
    }

    long long thr = (long long)n * 32;
    k_agg1<<<(unsigned)((thr + 255) / 256), 256>>>(n);
    k_relu_gemm2<<<(n + 15) / 16, 256>>>(b1, W2, n);
    k_agg2<<<(unsigned)((thr + 255) / 256), 256>>>(out, b2, n);
}

// round 13
// speedup vs baseline: 2.9754x; 1.2128x over previous
#include <cuda_runtime.h>
#include <cuda_fp16.h>
#include <cstdint>

#define NMAX   100000
#define EMAX   1600000
#define DIN    128
#define DH     128
#define DOUT   16

// ---------------- device scratch --------------------------------------------
__device__ __align__(16) float g_deg[NMAX];                 // dinv = rsqrt(deg+1)
__device__ __align__(16) uint2 g_h1h[(size_t)NMAX * 32];    // x @ W1 (half2 pairs)
__device__ __align__(16) float g_h2[(size_t)NMAX * DOUT];   // relu(...) @ W2 fp32
__device__ __align__(16) uint4 g_h2hx[(size_t)NMAX * 2];    // same, 16 halves/row
__device__ int g_csr[EMAX];
__device__ int g_cnt[NMAX];
__device__ int g_row[NMAX];
__device__ int g_cur[NMAX];
__device__ int g_excl[NMAX];
__device__ int g_bsum[128];
__device__ int g_is64;

// ---------------- helpers ---------------------------------------------------
__device__ __forceinline__ int load_idx(const void* __restrict__ ei, long long i) {
    if (g_is64) return (int)__ldg(((const long long*)ei) + i);
    return __ldg(((const int*)ei) + i);
}
__device__ __forceinline__ void ffma2(unsigned long long& d,
                                      unsigned long long a, unsigned long long b) {
    asm("fma.rn.f32x2 %0, %1, %2, %0;" : "+l"(d) : "l"(a), "l"(b));
}
__device__ __forceinline__ unsigned long long pack2(float lo, float hi) {
    unsigned long long r;
    asm("mov.b64 %0, {%1, %2};" : "=l"(r) : "f"(lo), "f"(hi));
    return r;
}
__device__ __forceinline__ float2 unpack2(unsigned long long v) {
    float lo, hi;
    asm("mov.b64 {%0, %1}, %2;" : "=f"(lo), "=f"(hi) : "l"(v));
    return make_float2(lo, hi);
}
__device__ __forceinline__ float2 h2f2(uint32_t u) {
    return __half22float2(*reinterpret_cast<__half2*>(&u));
}

// ---------------- CSR construction ------------------------------------------
__global__ void k_init(const void* __restrict__ ei, int n) {
    int i = blockIdx.x * blockDim.x + threadIdx.x;
    if (i < n) g_cnt[i] = 0;
    if (i == 0) {
        const unsigned long long* p = (const unsigned long long*)ei;
        int is64 = 1;
        for (int k = 0; k < 64; k++)
            if ((p[k] >> 32) != 0ull) { is64 = 0; break; }
        g_is64 = is64;
    }
}

__global__ void k_count(const void* __restrict__ ei, int e) {
    int i = blockIdx.x * blockDim.x + threadIdx.x;
    if (i < e) atomicAdd(&g_cnt[load_idx(ei, (long long)e + i)], 1);
}

__global__ void k_scan1(int n) {
    __shared__ int sh[256];
    int t = threadIdx.x;
    int base = blockIdx.x * 1024;
    int v[4], s = 0;
#pragma unroll
    for (int i = 0; i < 4; i++) {
        int idx = base + t * 4 + i;
        v[i] = (idx < n) ? g_cnt[idx] : 0;
        s += v[i];
    }
    sh[t] = s;
    __syncthreads();
    int own = s;
    for (int off = 1; off < 256; off <<= 1) {
        int o = (t >= off) ? sh[t - off] : 0;
        __syncthreads();
        sh[t] += o;
        __syncthreads();
    }
    if (t == 255) g_bsum[blockIdx.x] = sh[255];
    int run = sh[t] - own;
#pragma unroll
    for (int i = 0; i < 4; i++) {
        int idx = base + t * 4 + i;
        if (idx < n) g_excl[idx] = run;
        run += v[i];
    }
}

__global__ void k_scan2(int nb) {
    __shared__ int sh[128];
    int t = threadIdx.x;
    int v = (t < nb) ? g_bsum[t] : 0;
    sh[t] = v;
    __syncthreads();
    for (int off = 1; off < 128; off <<= 1) {
        int o = (t >= off) ? sh[t - off] : 0;
        __syncthreads();
        sh[t] += o;
        __syncthreads();
    }
    if (t < nb) g_bsum[t] = sh[t] - v;
}

__global__ void k_scan3(int n) {
    int i = blockIdx.x * blockDim.x + threadIdx.x;
    if (i < n) {
        int r = g_excl[i] + g_bsum[i >> 10];
        g_row[i] = r;
        g_cur[i] = r;
        g_deg[i] = rsqrtf((float)g_cnt[i] + 1.0f);
    }
}

__global__ void k_fill(const void* __restrict__ ei, int e) {
    int i = blockIdx.x * blockDim.x + threadIdx.x;
    if (i < e) {
        int s = load_idx(ei, i);
        int d = load_idx(ei, (long long)e + i);
        int pos = atomicAdd(&g_cur[d], 1);
        g_csr[pos] = s;
    }
}

// ---------------- GEMM1: h1h = fp16(x @ W1)  (FFMA2, transposed X tile) -----
// 64x128 tile / block, 256 thr. Accumulators pair ROWS (2p,2p+1) per column,
// so the a-operand loads directly as a 64-bit LDS (no re-pack); only the 4
// w-splat packs remain per k.
#define GTM 64
#define XTS 66          /* padded row stride of transposed X tile (even, 8B align) */
__global__ void k_gemm1(const float* __restrict__ x,
                        const float* __restrict__ W1, int n) {
    extern __shared__ float sm[];
    float* Ws = sm;                 // 128*128
    float* Xt = sm + DIN * DH;      // [DIN][XTS], transposed x tile
    int t = threadIdx.x;

    for (int i = t; i < DIN * DH / 4; i += 256)
        reinterpret_cast<float4*>(Ws)[i] = reinterpret_cast<const float4*>(W1)[i];

    int row0 = blockIdx.x * GTM;
    for (int i = t; i < GTM * 32; i += 256) {
        int r = i >> 5, c4 = i & 31;          // coalesced global read
        int gr = row0 + r;
        float4 v = make_float4(0.f, 0.f, 0.f, 0.f);
        if (gr < n) v = reinterpret_cast<const float4*>(x)[(size_t)gr * 32 + c4];
        Xt[(c4 * 4 + 0) * XTS + r] = v.x;      // transposed store (8-way conf, cheap)
        Xt[(c4 * 4 + 1) * XTS + r] = v.y;
        Xt[(c4 * 4 + 2) * XTS + r] = v.z;
        Xt[(c4 * 4 + 3) * XTS + r] = v.w;
    }
    __syncthreads();

    int cx = t & 31;    // column group (4 cols)
    int ry = t >> 5;    // row group (8 rows = 4 pairs)
    unsigned long long acc[4][4];   // [pair p][col c] = {row 2p, row 2p+1}
#pragma unroll
    for (int p = 0; p < 4; p++)
#pragma unroll
        for (int c = 0; c < 4; c++) acc[p][c] = 0ull;

#pragma unroll 4
    for (int k = 0; k < DIN; k++) {
        float4 w = reinterpret_cast<const float4*>(Ws)[k * 32 + cx];
        unsigned long long ws[4];
        ws[0] = pack2(w.x, w.x); ws[1] = pack2(w.y, w.y);
        ws[2] = pack2(w.z, w.z); ws[3] = pack2(w.w, w.w);
        const unsigned long long* arow =
            reinterpret_cast<const unsigned long long*>(&Xt[k * XTS + ry * 8]);
#pragma unroll
        for (int p = 0; p < 4; p++) {
            unsigned long long ap = arow[p];   // rows 2p,2p+1 (broadcast LDS.64)
            ffma2(acc[p][0], ap, ws[0]);
            ffma2(acc[p][1], ap, ws[1]);
            ffma2(acc[p][2], ap, ws[2]);
            ffma2(acc[p][3], ap, ws[3]);
        }
    }
#pragma unroll
    for (int p = 0; p < 4; p++) {
        int gr = row0 + ry * 8 + 2 * p;
        float2 c0 = unpack2(acc[p][0]);
        float2 c1 = unpack2(acc[p][1]);
        float2 c2 = unpack2(acc[p][2]);
        float2 c3 = unpack2(acc[p][3]);
        if (gr < n) {
            __half2 h0 = __floats2half2_rn(c0.x, c1.x);
            __half2 h1 = __floats2half2_rn(c2.x, c3.x);
            uint2 u;
            u.x = *reinterpret_cast<uint32_t*>(&h0);
            u.y = *reinterpret_cast<uint32_t*>(&h1);
            g_h1h[(size_t)gr * 32 + cx] = u;
        }
        if (gr + 1 < n) {
            __half2 h0 = __floats2half2_rn(c0.y, c1.y);
            __half2 h1 = __floats2half2_rn(c2.y, c3.y);
            uint2 u;
            u.x = *reinterpret_cast<uint32_t*>(&h0);
            u.y = *reinterpret_cast<uint32_t*>(&h1);
            g_h1h[(size_t)(gr + 1) * 32 + cx] = u;
        }
    }
}

// ---------------- fused layer 1: gather + relu + GEMM2 ----------------------
// 512 thr = 16 warps = 16 nodes/block. Phase 1: warp-per-node fp16 gather +
// self-loop + bias + relu -> smem row. Phase 2: 256 threads do 128x16 GEMV.
__global__ void __launch_bounds__(512) k_layer1(const float* __restrict__ b1,
                                                const float* __restrict__ W2, int n) {
    __shared__ float W2s[DH * DOUT];
    __shared__ float b1s[DH];
    __shared__ float vbuf[16 * 132];
    int t = threadIdx.x;
    for (int i = t; i < DH * DOUT; i += 512) W2s[i] = W2[i];
    if (t < DH) b1s[t] = b1[t];
    __syncthreads();

    int warp = t >> 5, lane = t & 31;
    int node = blockIdx.x * 16 + warp;
    if (node < n) {
        int beg = g_row[node];
        int end = beg + g_cnt[node];
        float4 acc = make_float4(0.f, 0.f, 0.f, 0.f);
        int p = beg;
        for (; p + 3 < end; p += 4) {
            int s0 = __ldg(&g_csr[p]),     s1 = __ldg(&g_csr[p + 1]);
            int s2 = __ldg(&g_csr[p + 2]), s3 = __ldg(&g_csr[p + 3]);
            float w0 = g_deg[s0], w1 = g_deg[s1], w2 = g_deg[s2], w3 = g_deg[s3];
            uint2 u0 = g_h1h[(size_t)s0 * 32 + lane];
            uint2 u1 = g_h1h[(size_t)s1 * 32 + lane];
            uint2 u2 = g_h1h[(size_t)s2 * 32 + lane];
            uint2 u3 = g_h1h[(size_t)s3 * 32 + lane];
            float2 a0 = h2f2(u0.x), b0 = h2f2(u0.y);
            float2 a1 = h2f2(u1.x), b1v = h2f2(u1.y);
            float2 a2 = h2f2(u2.x), b2v = h2f2(u2.y);
            float2 a3 = h2f2(u3.x), b3v = h2f2(u3.y);
            acc.x += a0.x * w0 + a1.x * w1 + a2.x * w2 + a3.x * w3;
            acc.y += a0.y * w0 + a1.y * w1 + a2.y * w2 + a3.y * w3;
            acc.z += b0.x * w0 + b1v.x * w1 + b2v.x * w2 + b3v.x * w3;
            acc.w += b0.y * w0 + b1v.y * w1 + b2v.y * w2 + b3v.y * w3;
        }
        for (; p < end; p++) {
            int s0 = __ldg(&g_csr[p]);
            float w0 = g_deg[s0];
            uint2 u0 = g_h1h[(size_t)s0 * 32 + lane];
            float2 a0 = h2f2(u0.x), b0 = h2f2(u0.y);
            acc.x = fmaf(a0.x, w0, acc.x);
            acc.y = fmaf(a0.y, w0, acc.y);
            acc.z = fmaf(b0.x, w0, acc.z);
            acc.w = fmaf(b0.y, w0, acc.w);
        }
        float di = g_deg[node];
        float dd = di * di;
        uint2 us = g_h1h[(size_t)node * 32 + lane];
        float2 s0 = h2f2(us.x), s1 = h2f2(us.y);
        float4 bb = *reinterpret_cast<const float4*>(&b1s[lane * 4]);
        float4 v;
        v.x = fmaxf(fmaf(acc.x, di, fmaf(s0.x, dd, bb.x)), 0.f);
        v.y = fmaxf(fmaf(acc.y, di, fmaf(s0.y, dd, bb.y)), 0.f);
        v.z = fmaxf(fmaf(acc.z, di, fmaf(s1.x, dd, bb.z)), 0.f);
        v.w = fmaxf(fmaf(acc.w, di, fmaf(s1.y, dd, bb.w)), 0.f);
        *reinterpret_cast<float4*>(&vbuf[warp * 132 + lane * 4]) = v;
    }
    __syncthreads();

    if (t < 256) {
        int nl = t >> 4;
        int node2 = blockIdx.x * 16 + nl;
        int j = t & 15;
        if (node2 < n) {
            const float* vr = &vbuf[nl * 132];
            float acc = 0.f;
#pragma unroll 8
            for (int k = 0; k < DH; k++)
                acc = fmaf(vr[k], W2s[k * DOUT + j], acc);
            g_h2[(size_t)node2 * DOUT + j] = acc;
            float nb = __shfl_xor_sync(0xffffffffu, acc, 1);
            if ((j & 1) == 0) {
                __half2 hp = __floats2half2_rn(acc, nb);
                ((uint32_t*)g_h2hx)[(size_t)node2 * 8 + (j >> 1)] =
                    *reinterpret_cast<uint32_t*>(&hp);
            }
        }
    }
}

// ---------------- layer-2 aggregation (fp16 gather) -------------------------
__global__ void k_agg2(float* __restrict__ out, const float* __restrict__ b2, int n) {
    long long tid = (long long)blockIdx.x * blockDim.x + threadIdx.x;
    int node = (int)(tid >> 5);
    int lane = threadIdx.x & 31;
    if (node >= n) return;
    int eg = lane >> 1;
    int ch = lane & 1;
    int beg = g_row[node];
    int end = beg + g_cnt[node];
    float4 acc = make_float4(0.f, 0.f, 0.f, 0.f);
    float4 acc2 = make_float4(0.f, 0.f, 0.f, 0.f);
    for (int p0 = beg; p0 < end; p0 += 16) {
        int p = p0 + eg;
        if (p < end) {
            int s = __ldg(&g_csr[p]);
            float w = g_deg[s];
            uint4 u = g_h2hx[(size_t)s * 2 + ch];
            float2 f0 = h2f2(u.x), f1 = h2f2(u.y), f2 = h2f2(u.z), f3 = h2f2(u.w);
            acc.x  = fmaf(f0.x, w, acc.x);
            acc.y  = fmaf(f0.y, w, acc.y);
            acc.z  = fmaf(f1.x, w, acc.z);
            acc.w  = fmaf(f1.y, w, acc.w);
            acc2.x = fmaf(f2.x, w, acc2.x);
            acc2.y = fmaf(f2.y, w, acc2.y);
            acc2.z = fmaf(f3.x, w, acc2.z);
            acc2.w = fmaf(f3.y, w, acc2.w);
        }
    }
#pragma unroll
    for (int m = 2; m <= 16; m <<= 1) {
        acc.x  += __shfl_xor_sync(0xffffffffu, acc.x,  m);
        acc.y  += __shfl_xor_sync(0xffffffffu, acc.y,  m);
        acc.z  += __shfl_xor_sync(0xffffffffu, acc.z,  m);
        acc.w  += __shfl_xor_sync(0xffffffffu, acc.w,  m);
        acc2.x += __shfl_xor_sync(0xffffffffu, acc2.x, m);
        acc2.y += __shfl_xor_sync(0xffffffffu, acc2.y, m);
        acc2.z += __shfl_xor_sync(0xffffffffu, acc2.z, m);
        acc2.w += __shfl_xor_sync(0xffffffffu, acc2.w, m);
    }
    if (lane < 2) {
        float di = g_deg[node];
        float dd = di * di;
        int c0 = lane * 2;
        float4 bb0 = reinterpret_cast<const float4*>(b2)[c0];
        float4 bb1 = reinterpret_cast<const float4*>(b2)[c0 + 1];
        float4 hv0 = reinterpret_cast<const float4*>(g_h2)[(size_t)node * 4 + c0];
        float4 hv1 = reinterpret_cast<const float4*>(g_h2)[(size_t)node * 4 + c0 + 1];
        float4 o0, o1;
        o0.x = bb0.x + fmaf(hv0.x, dd, acc.x  * di);
        o0.y = bb0.y + fmaf(hv0.y, dd, acc.y  * di);
        o0.z = bb0.z + fmaf(hv0.z, dd, acc.z  * di);
        o0.w = bb0.w + fmaf(hv0.w, dd, acc.w  * di);
        o1.x = bb1.x + fmaf(hv1.x, dd, acc2.x * di);
        o1.y = bb1.y + fmaf(hv1.y, dd, acc2.y * di);
        o1.z = bb1.z + fmaf(hv1.z, dd, acc2.z * di);
        o1.w = bb1.w + fmaf(hv1.w, dd, acc2.w * di);
        reinterpret_cast<float4*>(out)[(size_t)node * 4 + c0]     = o0;
        reinterpret_cast<float4*>(out)[(size_t)node * 4 + c0 + 1] = o1;
    }
}

// ---------------- launch -----------------------------------------------------
extern "C" void kernel_launch(void* const* d_in, const int* in_sizes, int n_in,
                              void* d_out, int out_size) {
    const float* x  = (const float*)d_in[0];
    const void*  ei = d_in[1];
    const float* W1 = (const float*)d_in[2];
    const float* b1 = (const float*)d_in[3];
    const float* W2 = (const float*)d_in[4];
    const float* b2 = (const float*)d_in[5];
    float* out = (float*)d_out;

    int n = in_sizes[0] / DIN;
    int e = in_sizes[1] / 2;

    static cudaStream_t s2 = 0;
    static cudaEvent_t evA = 0, evB = 0;
    static int tried = 0;
    if (!tried) {
        tried = 1;
        if (cudaStreamCreateWithFlags(&s2, cudaStreamNonBlocking) != cudaSuccess) s2 = 0;
        if (s2) {
            if (cudaEventCreateWithFlags(&evA, cudaEventDisableTiming) != cudaSuccess ||
                cudaEventCreateWithFlags(&evB, cudaEventDisableTiming) != cudaSuccess) {
                s2 = 0;
            }
        }
    }
    cudaStream_t sc = s2 ? s2 : 0;

    if (s2) {
        cudaEventRecord(evA, 0);
        cudaStreamWaitEvent(s2, evA, 0);
    }

    // CSR build (side stream) — independent of gemm1
    k_init<<<(n + 255) / 256, 256, 0, sc>>>(ei, n);
    k_count<<<(e + 255) / 256, 256, 0, sc>>>(ei, e);
    int nb = (n + 1023) / 1024;
    k_scan1<<<nb, 256, 0, sc>>>(n);
    k_scan2<<<1, 128, 0, sc>>>(nb);
    k_scan3<<<(n + 255) / 256, 256, 0, sc>>>(n);
    k_fill<<<(e + 255) / 256, 256, 0, sc>>>(ei, e);

    // GEMM1 (default stream, concurrent with CSR build)
    int smem = (DIN * DH + DIN * XTS) * (int)sizeof(float);   // ~97 KB
    cudaFuncSetAttribute(k_gemm1, cudaFuncAttributeMaxDynamicSharedMemorySize, smem);
    k_gemm1<<<(n + GTM - 1) / GTM, 256, smem>>>(x, W1, n);

    if (s2) {
        cudaEventRecord(evB, s2);
        cudaStreamWaitEvent(0, evB, 0);
    }

    k_layer1<<<(n + 15) / 16, 512>>>(b1, W2, n);
    long long thr = (long long)n * 32;
    k_agg2<<<(unsigned)((thr + 255) / 256), 256>>>(out, b2, n);
}